// round 4
// baseline (speedup 1.0000x reference)
#include <cuda_runtime.h>

#define NSEG 256
#define D 128
#define OUT_ELEMS (NSEG * D)

// Scratch (alloc-free rule: __device__ globals).
__device__ int g_counts[NSEG];
__device__ unsigned int g_done;

// ---------------------------------------------------------------------------
// Pass 0: zero output sums, counts, and the completion ticket.
// ---------------------------------------------------------------------------
__global__ void zero_kernel(float* __restrict__ out) {
    int i = blockIdx.x * blockDim.x + threadIdx.x;
    if (i < OUT_ELEMS) out[i] = 0.0f;
    if (i < NSEG) g_counts[i] = 0;
    if (i == 0) g_done = 0;
}

// ---------------------------------------------------------------------------
// Pass 1: segmented sum + fused finalize (last CTA divides by counts).
// One warp owns a contiguous row chunk; lane l holds float4 columns [4l,4l+4).
// Register accumulation; atomics only at segment boundaries / chunk end.
// ---------------------------------------------------------------------------
__device__ __forceinline__ void flush_acc(float* __restrict__ out, int seg_id,
                                          int lane, const float4& acc, int cnt) {
    float* p = out + seg_id * D + lane * 4;
    atomicAdd(p + 0, acc.x);
    atomicAdd(p + 1, acc.y);
    atomicAdd(p + 2, acc.z);
    atomicAdd(p + 3, acc.w);
    if (lane == 0) atomicAdd(&g_counts[seg_id], cnt);
}

__global__ __launch_bounds__(256) void segsum_kernel(
    const float4* __restrict__ inp,   // (n, 32) float4 view of (n, 128) float
    const int* __restrict__ seg,      // (n,) sorted segment ids
    float* __restrict__ out,          // (256, 128) sums -> means
    int n, int nblocks)
{
    const int lane = threadIdx.x & 31;
    const int warp_global = (blockIdx.x * blockDim.x + threadIdx.x) >> 5;
    const int num_warps = (nblocks * (int)blockDim.x) >> 5;

    const int rows_per_warp = (n + num_warps - 1) / num_warps;
    int r = warp_global * rows_per_warp;
    const int r1 = min(n, r + rows_per_warp);

    if (r < r1) {
        float4 acc = make_float4(0.0f, 0.0f, 0.0f, 0.0f);
        int cnt = 0;
        int cur = __ldg(seg + r);

        // Fast path: 8 rows per iteration. Batch all loads first (MLP=8+),
        // then accumulate. Sorted ids => s0==cur && s7==cur implies all equal.
        while (r + 8 <= r1) {
            int s0 = __ldg(seg + r);
            int s7 = __ldg(seg + r + 7);
            const float4* base = inp + (size_t)r * 32 + lane;
            float4 v0 = __ldcs(base + 0 * 32);
            float4 v1 = __ldcs(base + 1 * 32);
            float4 v2 = __ldcs(base + 2 * 32);
            float4 v3 = __ldcs(base + 3 * 32);
            float4 v4 = __ldcs(base + 4 * 32);
            float4 v5 = __ldcs(base + 5 * 32);
            float4 v6 = __ldcs(base + 6 * 32);
            float4 v7 = __ldcs(base + 7 * 32);
            if (s0 == cur && s7 == cur) {
                // Pairwise tree to shorten the dependency chain.
                float ax = ((v0.x + v1.x) + (v2.x + v3.x)) + ((v4.x + v5.x) + (v6.x + v7.x));
                float ay = ((v0.y + v1.y) + (v2.y + v3.y)) + ((v4.y + v5.y) + (v6.y + v7.y));
                float az = ((v0.z + v1.z) + (v2.z + v3.z)) + ((v4.z + v5.z) + (v6.z + v7.z));
                float aw = ((v0.w + v1.w) + (v2.w + v3.w)) + ((v4.w + v5.w) + (v6.w + v7.w));
                acc.x += ax; acc.y += ay; acc.z += az; acc.w += aw;
                cnt += 8;
            } else {
                // Boundary inside this octet: row-by-row.
                int ss[8];
                ss[0] = s0; ss[7] = s7;
                #pragma unroll
                for (int i = 1; i < 7; ++i) ss[i] = __ldg(seg + r + i);
                float4 vv[8] = {v0, v1, v2, v3, v4, v5, v6, v7};
                #pragma unroll
                for (int i = 0; i < 8; ++i) {
                    if (ss[i] != cur) {
                        flush_acc(out, cur, lane, acc, cnt);
                        acc = make_float4(0.0f, 0.0f, 0.0f, 0.0f);
                        cnt = 0;
                        cur = ss[i];
                    }
                    acc.x += vv[i].x; acc.y += vv[i].y;
                    acc.z += vv[i].z; acc.w += vv[i].w;
                    cnt++;
                }
            }
            r += 8;
        }

        // Tail rows.
        for (; r < r1; ++r) {
            int s = __ldg(seg + r);
            float4 v = __ldcs(inp + (size_t)r * 32 + lane);
            if (s != cur) {
                flush_acc(out, cur, lane, acc, cnt);
                acc = make_float4(0.0f, 0.0f, 0.0f, 0.0f);
                cnt = 0;
                cur = s;
            }
            acc.x += v.x; acc.y += v.y; acc.z += v.z; acc.w += v.w;
            cnt++;
        }

        flush_acc(out, cur, lane, acc, cnt);
    }

    // ---- Fused finalize: last CTA to finish divides sums by counts. ----
    __shared__ unsigned int s_is_last;
    __threadfence();             // release our atomics before taking a ticket
    __syncthreads();             // all warps of this CTA have flushed
    if (threadIdx.x == 0) {
        unsigned int ticket = atomicAdd(&g_done, 1u);
        s_is_last = (ticket == (unsigned int)(nblocks - 1)) ? 1u : 0u;
    }
    __syncthreads();
    if (s_is_last) {
        // All other CTAs' atomics are globally visible (fence-before-ticket).
        float4* o4 = (float4*)out;
        for (int j = threadIdx.x; j < OUT_ELEMS / 4; j += blockDim.x) {
            int s = j >> 5;                    // float4 index -> segment (32 f4/row)
            int c = g_counts[s];
            float inv = 1.0f / (float)(c < 1 ? 1 : c);
            float4 v = o4[j];
            v.x *= inv; v.y *= inv; v.z *= inv; v.w *= inv;
            o4[j] = v;
        }
    }
}

// ---------------------------------------------------------------------------
// Launch. d_in[0] = inp (float32, n*128), d_in[1] = batch_seg (int32, n).
// Output: (256, 128) float32 means.
// ---------------------------------------------------------------------------
extern "C" void kernel_launch(void* const* d_in, const int* in_sizes, int n_in,
                              void* d_out, int out_size) {
    const float* inp = (const float*)d_in[0];
    const int* seg = (const int*)d_in[1];
    float* out = (float*)d_out;
    const int n = in_sizes[1];  // number of rows

    zero_kernel<<<(OUT_ELEMS + 255) / 256, 256>>>(out);

    const int blocks = 148 * 8;  // full first wave regardless of occupancy limit
    segsum_kernel<<<blocks, 256>>>((const float4*)inp, seg, out, n, blocks);
}